// round 11
// baseline (speedup 1.0000x reference)
#include <cuda_runtime.h>
#include <math.h>

#define KK 128
#define NNODES 2048
#define DD 512
#define NSPLIT 4

__device__ float g_p1[NSPLIT * KK * DD];   // split-K partials of ctx @ Wq^T
__device__ float g_p2[NSPLIT * KK * DD];   // split-K partials of cq @ Wk
__device__ float g_compat[KK * NNODES];    // masked exp(tanh(clip(dot))/sqrt(D))
__device__ float g_wsum[KK * 64];          // per-chunk partial row sums
__device__ int   g_mask_i32;

// ---------------------------------------------------------------------------
// Register-tiled split-K projection GEMMs.
// Grid 256 = 8 ntiles(64) x 8 ktiles(16) x 4 splits. Block 128 threads.
// Thread = (kq 0..7, nq 0..15) owns 2k x 4n outputs.
//   STAGE1==false: A = ctx, B = Wq (NT): out[k,n] = sum_m A[k,m]*Wq[n,m]
//                  Bs stored [n][m] (natural copy of Wq rows).
//   STAGE1==true : A = sum_s g_p1[s], B = Wk (NN): out[k,n] = sum_m A[k,m]*Wk[m,n]
//                  Bs stored [m][n] (natural copy of Wk rows).
// Inner 4-m group: 2+4 LDS.128 + 32 FFMA.
// Stage-1 block 0 also probes mask dtype (512 words all in {0,1} => int32).
// ---------------------------------------------------------------------------
template<bool STAGE1>
__global__ void __launch_bounds__(128) proj_gemm_rt(const float* __restrict__ Ain,
                                                    const float* __restrict__ B,
                                                    const int* __restrict__ m32) {
    __shared__ float As[16][132];                 // [k][m]
    __shared__ float BsA[STAGE1 ? 1 : 64][STAGE1 ? 1 : 132];  // stage1: [n][m]
    __shared__ float BsB[STAGE1 ? 128 : 1][STAGE1 ? 68 : 1];  // stage2: [m][n]

    const int t   = threadIdx.x;
    const int bx  = blockIdx.x;
    const int nt  = (bx & 7) * 64;
    const int ktb = ((bx >> 3) & 7) * 16;
    const int sp  = bx >> 6;
    const int mt  = sp * 128;
    const int kq  = t >> 4;                       // 0..7 -> k = ktb + 2*kq + i
    const int nq  = t & 15;                       // 0..15 -> n = nt + 4*nq + j

    if (!STAGE1 && bx == 0) {
        int v0 = m32[t], v1 = m32[t + 128], v2 = m32[t + 256], v3 = m32[t + 384];
        bool bad = (v0 | v1 | v2 | v3) >> 1;      // any value outside {0,1}
        bool any = __syncthreads_or(bad);
        if (t == 0) g_mask_i32 = any ? 0 : 1;
    }

    // ---- As: 16 x 128 floats (4 float4/thread), coalesced ----
#pragma unroll
    for (int s = 0; s < 4; ++s) {
        int idx = t + s * 128;                    // 0..511 float4
        int r = idx >> 5, c4 = idx & 31;
        if (!STAGE1) {
            *reinterpret_cast<float4*>(&As[r][c4 * 4]) =
                *reinterpret_cast<const float4*>(Ain + (ktb + r) * DD + mt + c4 * 4);
        } else {
            const int off = (ktb + r) * DD + mt + c4 * 4;
            float4 a = *reinterpret_cast<const float4*>(g_p1 + off);
            float4 b = *reinterpret_cast<const float4*>(g_p1 + KK * DD + off);
            float4 c = *reinterpret_cast<const float4*>(g_p1 + 2 * KK * DD + off);
            float4 d = *reinterpret_cast<const float4*>(g_p1 + 3 * KK * DD + off);
            *reinterpret_cast<float4*>(&As[r][c4 * 4]) =
                make_float4(a.x+b.x+c.x+d.x, a.y+b.y+c.y+d.y,
                            a.z+b.z+c.z+d.z, a.w+b.w+c.w+d.w);
        }
    }
    // ---- Bs: 8192 floats (16 float4/thread), coalesced natural copies ----
#pragma unroll
    for (int s = 0; s < 16; ++s) {
        int idx = t + s * 128;                    // 0..2047 float4
        if (!STAGE1) {                            // Bs[n][m] = Wq[nt+n][mt+m]
            int n = idx >> 5, c4 = idx & 31;
            *reinterpret_cast<float4*>(&BsA[n][c4 * 4]) =
                *reinterpret_cast<const float4*>(B + (nt + n) * DD + mt + c4 * 4);
        } else {                                  // Bs[m][n] = Wk[mt+m][nt+n]
            int m = idx >> 4, c4 = idx & 15;
            *reinterpret_cast<float4*>(&BsB[m][c4 * 4]) =
                *reinterpret_cast<const float4*>(B + (mt + m) * DD + nt + c4 * 4);
        }
    }
    __syncthreads();

    float acc[2][4];
#pragma unroll
    for (int i = 0; i < 2; ++i)
#pragma unroll
        for (int j = 0; j < 4; ++j) acc[i][j] = 0.f;

#pragma unroll 4
    for (int mg = 0; mg < 32; ++mg) {
        float4 a0 = *reinterpret_cast<const float4*>(&As[2 * kq + 0][4 * mg]);
        float4 a1 = *reinterpret_cast<const float4*>(&As[2 * kq + 1][4 * mg]);
        float4 av[2] = {a0, a1};
        if (!STAGE1) {
            float4 b0 = *reinterpret_cast<const float4*>(&BsA[4 * nq + 0][4 * mg]);
            float4 b1 = *reinterpret_cast<const float4*>(&BsA[4 * nq + 1][4 * mg]);
            float4 b2 = *reinterpret_cast<const float4*>(&BsA[4 * nq + 2][4 * mg]);
            float4 b3 = *reinterpret_cast<const float4*>(&BsA[4 * nq + 3][4 * mg]);
            float4 bv[4] = {b0, b1, b2, b3};
#pragma unroll
            for (int i = 0; i < 2; ++i)
#pragma unroll
                for (int j = 0; j < 4; ++j)
                    acc[i][j] += av[i].x * bv[j].x + av[i].y * bv[j].y
                               + av[i].z * bv[j].z + av[i].w * bv[j].w;
        } else {
            float4 b0 = *reinterpret_cast<const float4*>(&BsB[4 * mg + 0][4 * nq]);
            float4 b1 = *reinterpret_cast<const float4*>(&BsB[4 * mg + 1][4 * nq]);
            float4 b2 = *reinterpret_cast<const float4*>(&BsB[4 * mg + 2][4 * nq]);
            float4 b3 = *reinterpret_cast<const float4*>(&BsB[4 * mg + 3][4 * nq]);
#pragma unroll
            for (int i = 0; i < 2; ++i) {
                acc[i][0] += av[i].x * b0.x + av[i].y * b1.x + av[i].z * b2.x + av[i].w * b3.x;
                acc[i][1] += av[i].x * b0.y + av[i].y * b1.y + av[i].z * b2.y + av[i].w * b3.y;
                acc[i][2] += av[i].x * b0.z + av[i].y * b1.z + av[i].z * b2.z + av[i].w * b3.z;
                acc[i][3] += av[i].x * b0.w + av[i].y * b1.w + av[i].z * b2.w + av[i].w * b3.w;
            }
        }
    }

    float* Out = (STAGE1 ? g_p2 : g_p1) + (size_t)sp * KK * DD;
#pragma unroll
    for (int i = 0; i < 2; ++i) {
        int k = ktb + 2 * kq + i;
        *reinterpret_cast<float4*>(Out + k * DD + nt + 4 * nq) =
            make_float4(acc[i][0], acc[i][1], acc[i][2], acc[i][3]);
    }
}

// ---------------------------------------------------------------------------
// Streaming compat + fused masked exp + per-warp row-sum partial.
// Grid 2048 x 128 threads. Global warp g: k = g>>6, chunk = g&63, i0 = chunk*32.
// |v| <= tanh(10)/sqrt(512) ~ 0.0442 -> exp cannot overflow, no max-shift.
// ---------------------------------------------------------------------------
__global__ void __launch_bounds__(128) compat_kernel(const float* __restrict__ node,
                                                     const void* __restrict__ maskp) {
    __shared__ float part[4][32][33];

    const int lane = threadIdx.x & 31;
    const int w    = threadIdx.x >> 5;
    const int g    = blockIdx.x * 4 + w;
    const int k    = g >> 6;
    const int chunk= g & 63;
    const int i0   = chunk * 32;

    // q[k] = sum of 4 stage-2 split partials
    const float4* p2 = reinterpret_cast<const float4*>(g_p2);
    float4 q0, q1, q2, q3;
    {
        const int rs = DD / 4;
#pragma unroll
        for (int seg = 0; seg < 4; ++seg) {
            float4 a0 = p2[(0 * KK + k) * rs + seg * 32 + lane];
            float4 b0 = p2[(1 * KK + k) * rs + seg * 32 + lane];
            float4 c0 = p2[(2 * KK + k) * rs + seg * 32 + lane];
            float4 d0 = p2[(3 * KK + k) * rs + seg * 32 + lane];
            float4 q = make_float4(a0.x+b0.x+c0.x+d0.x, a0.y+b0.y+c0.y+d0.y,
                                   a0.z+b0.z+c0.z+d0.z, a0.w+b0.w+c0.w+d0.w);
            if (seg == 0) q0 = q; else if (seg == 1) q1 = q;
            else if (seg == 2) q2 = q; else q3 = q;
        }
    }

    const float4* base = reinterpret_cast<const float4*>(node)
                       + ((size_t)(k * NNODES + i0) << 7);

#pragma unroll 4
    for (int ii = 0; ii < 32; ++ii) {
        const float4* p = base + ((size_t)ii << 7);
        float4 v0 = __ldcs(p + lane);
        float4 v1 = __ldcs(p + 32 + lane);
        float4 v2 = __ldcs(p + 64 + lane);
        float4 v3 = __ldcs(p + 96 + lane);
        float a0 = v0.x * q0.x + v0.y * q0.y + v0.z * q0.z + v0.w * q0.w;
        float a1 = v1.x * q1.x + v1.y * q1.y + v1.z * q1.z + v1.w * q1.w;
        float a2 = v2.x * q2.x + v2.y * q2.y + v2.z * q2.z + v2.w * q2.w;
        float a3 = v3.x * q3.x + v3.y * q3.y + v3.z * q3.z + v3.w * q3.w;
        part[w][ii][lane] = (a0 + a1) + (a2 + a3);
    }
    __syncwarp();

    float s0 = 0.f, s1 = 0.f, s2 = 0.f, s3 = 0.f;
#pragma unroll
    for (int j = 0; j < 32; j += 4) {
        s0 += part[w][lane][j];
        s1 += part[w][lane][j + 1];
        s2 += part[w][lane][j + 2];
        s3 += part[w][lane][j + 3];
    }
    float a = (s0 + s1) + (s2 + s3);
    float c = fminf(10.f, fmaxf(-10.f, a));
    float v = tanhf(c) * 0.04419417382415922f;   // 1/sqrt(512)

    bool msk;
    if (g_mask_i32) {
        msk = reinterpret_cast<const int*>(maskp)[k * NNODES + i0 + lane] != 0;
    } else {
        msk = reinterpret_cast<const unsigned char*>(maskp)[k * NNODES + i0 + lane] != 0;
    }
    float e = msk ? 0.f : __expf(v);
    g_compat[k * NNODES + i0 + lane] = e;

    float ws = e;
#pragma unroll
    for (int off = 16; off; off >>= 1)
        ws += __shfl_xor_sync(0xffffffffu, ws, off);
    if (lane == 0) g_wsum[k * 64 + chunk] = ws;
}

// ---------------------------------------------------------------------------
// Normalize: grid 512 (4 blocks/row) x 128 threads, 1 float4/thread.
// Row sum by warp 0 via shfl (no barrier tree), single __syncthreads bcast.
// ---------------------------------------------------------------------------
__global__ void __launch_bounds__(128) norm_kernel(float* __restrict__ out) {
    __shared__ float sinv;
    const int b = blockIdx.x;
    const int k = b >> 2;
    const int t = threadIdx.x;

    if (t < 32) {
        float s = g_wsum[k * 64 + t] + g_wsum[k * 64 + 32 + t];
#pragma unroll
        for (int off = 16; off; off >>= 1)
            s += __shfl_xor_sync(0xffffffffu, s, off);
        if (t == 0) sinv = 1.0f / s;
    }
    __syncthreads();
    const float inv = sinv;

    const int idx4 = k * (NNODES / 4) + (b & 3) * 128 + t;
    const float4* c4 = reinterpret_cast<const float4*>(g_compat);
    float4* o4 = reinterpret_cast<float4*>(out);
    float4 v = c4[idx4];
    o4[idx4] = make_float4(v.x * inv, v.y * inv, v.z * inv, v.w * inv);
}

extern "C" void kernel_launch(void* const* d_in, const int* in_sizes, int n_in,
                              void* d_out, int out_size) {
    const float* ctx  = (const float*)d_in[0];
    const float* node = (const float*)d_in[1];
    const void*  mask = d_in[2];
    const float* Wq   = (const float*)d_in[3];
    const float* Wk   = (const float*)d_in[4];
    float* out = (float*)d_out;
    (void)in_sizes; (void)n_in; (void)out_size;

    proj_gemm_rt<false><<<256, 128>>>(ctx, Wq, (const int*)mask);  // g_p1
    proj_gemm_rt<true ><<<256, 128>>>(nullptr, Wk, nullptr);       // g_p2
    compat_kernel<<<KK * 16, 128>>>(node, mask);                   // exp + partials
    norm_kernel<<<512, 128>>>(out);                                // row-normalize
}

// round 13
// speedup vs baseline: 1.0187x; 1.0187x over previous
#include <cuda_runtime.h>
#include <math.h>

#define KK 128
#define NNODES 2048
#define DD 512
#define NSPLIT 4

__device__ float g_p1[NSPLIT * KK * DD];   // split-K partials of ctx @ Wq^T
__device__ float g_p2[NSPLIT * KK * DD];   // split-K partials of cq @ Wk
__device__ float g_compat[KK * NNODES];    // masked exp(tanh(clip(dot))/sqrt(D))
__device__ float g_wsum[KK * 64];          // per-chunk partial row sums
__device__ int   g_mask_i32;

// ---------------------------------------------------------------------------
// Register-tiled split-K projection GEMMs (R10 shape — measured best).
// Grid 128 = 8 ntiles(64) x 4 ktiles(32) x 4 splits. Block 128 threads.
// Thread = (kq 0..7, nq 0..15) owns 4k x 4n outputs.
// ---------------------------------------------------------------------------
template<bool STAGE1>
__global__ void __launch_bounds__(128) proj_gemm_rt(const float* __restrict__ Ain,
                                                    const float* __restrict__ B,
                                                    const int* __restrict__ m32) {
    __shared__ float As[32][132];
    __shared__ float BsA[STAGE1 ? 1 : 64][STAGE1 ? 1 : 132];  // stage1: [n][m]
    __shared__ float BsB[STAGE1 ? 128 : 1][STAGE1 ? 68 : 1];  // stage2: [m][n]

    const int t   = threadIdx.x;
    const int bx  = blockIdx.x;
    const int nt  = (bx & 7) * 64;
    const int ktb = ((bx >> 3) & 3) * 32;
    const int sp  = bx >> 5;
    const int mt  = sp * 128;
    const int kq  = t >> 4;
    const int nq  = t & 15;

    if (!STAGE1 && bx == 0) {
        int v0 = m32[t], v1 = m32[t + 128], v2 = m32[t + 256], v3 = m32[t + 384];
        bool bad = (v0 | v1 | v2 | v3) >> 1;
        bool any = __syncthreads_or(bad);
        if (t == 0) g_mask_i32 = any ? 0 : 1;
    }

#pragma unroll
    for (int s = 0; s < 8; ++s) {
        int idx = t + s * 128;
        int r = idx >> 5, c4 = idx & 31;
        if (!STAGE1) {
            *reinterpret_cast<float4*>(&As[r][c4 * 4]) =
                *reinterpret_cast<const float4*>(Ain + (ktb + r) * DD + mt + c4 * 4);
        } else {
            const int off = (ktb + r) * DD + mt + c4 * 4;
            float4 a = *reinterpret_cast<const float4*>(g_p1 + off);
            float4 b = *reinterpret_cast<const float4*>(g_p1 + KK * DD + off);
            float4 c = *reinterpret_cast<const float4*>(g_p1 + 2 * KK * DD + off);
            float4 d = *reinterpret_cast<const float4*>(g_p1 + 3 * KK * DD + off);
            *reinterpret_cast<float4*>(&As[r][c4 * 4]) =
                make_float4(a.x+b.x+c.x+d.x, a.y+b.y+c.y+d.y,
                            a.z+b.z+c.z+d.z, a.w+b.w+c.w+d.w);
        }
    }
#pragma unroll
    for (int s = 0; s < 16; ++s) {
        int idx = t + s * 128;
        if (!STAGE1) {                            // Bs[n][m] = Wq[nt+n][mt+m]
            int n = idx >> 5, c4 = idx & 31;
            *reinterpret_cast<float4*>(&BsA[n][c4 * 4]) =
                *reinterpret_cast<const float4*>(B + (nt + n) * DD + mt + c4 * 4);
        } else {                                  // Bs[m][n] = Wk[mt+m][nt+n]
            int m = idx >> 4, c4 = idx & 15;
            *reinterpret_cast<float4*>(&BsB[m][c4 * 4]) =
                *reinterpret_cast<const float4*>(B + (mt + m) * DD + nt + c4 * 4);
        }
    }
    __syncthreads();

    float acc[4][4];
#pragma unroll
    for (int i = 0; i < 4; ++i)
#pragma unroll
        for (int j = 0; j < 4; ++j) acc[i][j] = 0.f;

#pragma unroll 4
    for (int mg = 0; mg < 32; ++mg) {
        float4 a0 = *reinterpret_cast<const float4*>(&As[4 * kq + 0][4 * mg]);
        float4 a1 = *reinterpret_cast<const float4*>(&As[4 * kq + 1][4 * mg]);
        float4 a2 = *reinterpret_cast<const float4*>(&As[4 * kq + 2][4 * mg]);
        float4 a3 = *reinterpret_cast<const float4*>(&As[4 * kq + 3][4 * mg]);
        float4 av[4] = {a0, a1, a2, a3};
        if (!STAGE1) {
            float4 b0 = *reinterpret_cast<const float4*>(&BsA[4 * nq + 0][4 * mg]);
            float4 b1 = *reinterpret_cast<const float4*>(&BsA[4 * nq + 1][4 * mg]);
            float4 b2 = *reinterpret_cast<const float4*>(&BsA[4 * nq + 2][4 * mg]);
            float4 b3 = *reinterpret_cast<const float4*>(&BsA[4 * nq + 3][4 * mg]);
            float4 bv[4] = {b0, b1, b2, b3};
#pragma unroll
            for (int i = 0; i < 4; ++i)
#pragma unroll
                for (int j = 0; j < 4; ++j)
                    acc[i][j] += av[i].x * bv[j].x + av[i].y * bv[j].y
                               + av[i].z * bv[j].z + av[i].w * bv[j].w;
        } else {
            float4 b0 = *reinterpret_cast<const float4*>(&BsB[4 * mg + 0][4 * nq]);
            float4 b1 = *reinterpret_cast<const float4*>(&BsB[4 * mg + 1][4 * nq]);
            float4 b2 = *reinterpret_cast<const float4*>(&BsB[4 * mg + 2][4 * nq]);
            float4 b3 = *reinterpret_cast<const float4*>(&BsB[4 * mg + 3][4 * nq]);
#pragma unroll
            for (int i = 0; i < 4; ++i) {
                acc[i][0] += av[i].x * b0.x + av[i].y * b1.x + av[i].z * b2.x + av[i].w * b3.x;
                acc[i][1] += av[i].x * b0.y + av[i].y * b1.y + av[i].z * b2.y + av[i].w * b3.y;
                acc[i][2] += av[i].x * b0.z + av[i].y * b1.z + av[i].z * b2.z + av[i].w * b3.z;
                acc[i][3] += av[i].x * b0.w + av[i].y * b1.w + av[i].z * b2.w + av[i].w * b3.w;
            }
        }
    }

    float* Out = (STAGE1 ? g_p2 : g_p1) + (size_t)sp * KK * DD;
#pragma unroll
    for (int i = 0; i < 4; ++i) {
        int k = ktb + 4 * kq + i;
        *reinterpret_cast<float4*>(Out + k * DD + nt + 4 * nq) =
            make_float4(acc[i][0], acc[i][1], acc[i][2], acc[i][3]);
    }
}

// ---------------------------------------------------------------------------
// Streaming compat + fused masked exp + per-warp row-sum partial.
// Grid 2048 x 128 threads. Global warp g: k = g>>6, chunk = g&63, i0 = chunk*32.
// Mask load hoisted before the streaming loop; main loop unroll 8 for MLP.
// ---------------------------------------------------------------------------
__global__ void __launch_bounds__(128) compat_kernel(const float* __restrict__ node,
                                                     const void* __restrict__ maskp) {
    __shared__ float part[4][32][33];

    const int lane = threadIdx.x & 31;
    const int w    = threadIdx.x >> 5;
    const int g    = blockIdx.x * 4 + w;
    const int k    = g >> 6;
    const int chunk= g & 63;
    const int i0   = chunk * 32;

    // mask bit for this thread's node (hoisted: latency hides under the stream)
    bool msk;
    if (g_mask_i32) {
        msk = __ldg(reinterpret_cast<const int*>(maskp) + k * NNODES + i0 + lane) != 0;
    } else {
        msk = __ldg(reinterpret_cast<const unsigned char*>(maskp) + k * NNODES + i0 + lane) != 0;
    }

    // q[k] = sum of 4 stage-2 split partials
    const float4* p2 = reinterpret_cast<const float4*>(g_p2);
    float4 q0, q1, q2, q3;
    {
        const int rs = DD / 4;
#pragma unroll
        for (int seg = 0; seg < 4; ++seg) {
            float4 a0 = p2[(0 * KK + k) * rs + seg * 32 + lane];
            float4 b0 = p2[(1 * KK + k) * rs + seg * 32 + lane];
            float4 c0 = p2[(2 * KK + k) * rs + seg * 32 + lane];
            float4 d0 = p2[(3 * KK + k) * rs + seg * 32 + lane];
            float4 q = make_float4(a0.x+b0.x+c0.x+d0.x, a0.y+b0.y+c0.y+d0.y,
                                   a0.z+b0.z+c0.z+d0.z, a0.w+b0.w+c0.w+d0.w);
            if (seg == 0) q0 = q; else if (seg == 1) q1 = q;
            else if (seg == 2) q2 = q; else q3 = q;
        }
    }

    const float4* base = reinterpret_cast<const float4*>(node)
                       + ((size_t)(k * NNODES + i0) << 7);

#pragma unroll 8
    for (int ii = 0; ii < 32; ++ii) {
        const float4* p = base + ((size_t)ii << 7);
        float4 v0 = __ldcs(p + lane);
        float4 v1 = __ldcs(p + 32 + lane);
        float4 v2 = __ldcs(p + 64 + lane);
        float4 v3 = __ldcs(p + 96 + lane);
        float a0 = v0.x * q0.x + v0.y * q0.y + v0.z * q0.z + v0.w * q0.w;
        float a1 = v1.x * q1.x + v1.y * q1.y + v1.z * q1.z + v1.w * q1.w;
        float a2 = v2.x * q2.x + v2.y * q2.y + v2.z * q2.z + v2.w * q2.w;
        float a3 = v3.x * q3.x + v3.y * q3.y + v3.z * q3.z + v3.w * q3.w;
        part[w][ii][lane] = (a0 + a1) + (a2 + a3);
    }
    __syncwarp();

    float s0 = 0.f, s1 = 0.f, s2 = 0.f, s3 = 0.f;
#pragma unroll
    for (int j = 0; j < 32; j += 4) {
        s0 += part[w][lane][j];
        s1 += part[w][lane][j + 1];
        s2 += part[w][lane][j + 2];
        s3 += part[w][lane][j + 3];
    }
    float a = (s0 + s1) + (s2 + s3);
    float c = fminf(10.f, fmaxf(-10.f, a));
    float v = tanhf(c) * 0.04419417382415922f;   // 1/sqrt(512)

    float e = msk ? 0.f : __expf(v);
    g_compat[k * NNODES + i0 + lane] = e;

    float ws = e;
#pragma unroll
    for (int off = 16; off; off >>= 1)
        ws += __shfl_xor_sync(0xffffffffu, ws, off);
    if (lane == 0) g_wsum[k * 64 + chunk] = ws;
}

// ---------------------------------------------------------------------------
// Normalize: grid 256 (2 blocks/row) x 256 threads (R8 shape).
// ---------------------------------------------------------------------------
__global__ void __launch_bounds__(256) norm_kernel(float* __restrict__ out) {
    __shared__ float sinv;
    const int b = blockIdx.x;
    const int k = b >> 1;
    const int t = threadIdx.x;

    if (t < 32) {
        float s = g_wsum[k * 64 + t] + g_wsum[k * 64 + 32 + t];
#pragma unroll
        for (int off = 16; off; off >>= 1)
            s += __shfl_xor_sync(0xffffffffu, s, off);
        if (t == 0) sinv = 1.0f / s;
    }
    __syncthreads();
    const float inv = sinv;

    const int idx4 = k * (NNODES / 4) + (b & 1) * 256 + t;
    const float4* c4 = reinterpret_cast<const float4*>(g_compat);
    float4* o4 = reinterpret_cast<float4*>(out);
    float4 v = c4[idx4];
    o4[idx4] = make_float4(v.x * inv, v.y * inv, v.z * inv, v.w * inv);
}

extern "C" void kernel_launch(void* const* d_in, const int* in_sizes, int n_in,
                              void* d_out, int out_size) {
    const float* ctx  = (const float*)d_in[0];
    const float* node = (const float*)d_in[1];
    const void*  mask = d_in[2];
    const float* Wq   = (const float*)d_in[3];
    const float* Wk   = (const float*)d_in[4];
    float* out = (float*)d_out;
    (void)in_sizes; (void)n_in; (void)out_size;

    proj_gemm_rt<false><<<128, 128>>>(ctx, Wq, (const int*)mask);  // g_p1
    proj_gemm_rt<true ><<<128, 128>>>(nullptr, Wk, nullptr);       // g_p2
    compat_kernel<<<KK * 16, 128>>>(node, mask);                   // exp + partials
    norm_kernel<<<256, 256>>>(out);                                // row-normalize
}

// round 14
// speedup vs baseline: 1.0727x; 1.0529x over previous
#include <cuda_runtime.h>
#include <cooperative_groups.h>
#include <math.h>

namespace cg = cooperative_groups;

#define KK 128
#define NNODES 2048
#define DD 512
#define NSPLIT 4

__device__ float g_p1[NSPLIT * KK * DD];   // split-K partials of ctx @ Wq^T
__device__ float g_p2[NSPLIT * KK * DD];   // split-K partials of cq @ Wk
__device__ int   g_mask_i32;

// ---------------------------------------------------------------------------
// Register-tiled split-K projection GEMMs (R10 shape — measured best).
// Grid 128 = 8 ntiles(64) x 4 ktiles(32) x 4 splits. Block 128 threads.
// Thread = (kq 0..7, nq 0..15) owns 4k x 4n outputs.
// Stage-1 block 0 also probes mask dtype (512 words all in {0,1} => int32).
// ---------------------------------------------------------------------------
template<bool STAGE1>
__global__ void __launch_bounds__(128) proj_gemm_rt(const float* __restrict__ Ain,
                                                    const float* __restrict__ B,
                                                    const int* __restrict__ m32) {
    __shared__ float As[32][132];
    __shared__ float BsA[STAGE1 ? 1 : 64][STAGE1 ? 1 : 132];  // stage1: [n][m]
    __shared__ float BsB[STAGE1 ? 128 : 1][STAGE1 ? 68 : 1];  // stage2: [m][n]

    const int t   = threadIdx.x;
    const int bx  = blockIdx.x;
    const int nt  = (bx & 7) * 64;
    const int ktb = ((bx >> 3) & 3) * 32;
    const int sp  = bx >> 5;
    const int mt  = sp * 128;
    const int kq  = t >> 4;
    const int nq  = t & 15;

    if (!STAGE1 && bx == 0) {
        int v0 = m32[t], v1 = m32[t + 128], v2 = m32[t + 256], v3 = m32[t + 384];
        bool bad = (v0 | v1 | v2 | v3) >> 1;
        bool any = __syncthreads_or(bad);
        if (t == 0) g_mask_i32 = any ? 0 : 1;
    }

#pragma unroll
    for (int s = 0; s < 8; ++s) {
        int idx = t + s * 128;
        int r = idx >> 5, c4 = idx & 31;
        if (!STAGE1) {
            *reinterpret_cast<float4*>(&As[r][c4 * 4]) =
                *reinterpret_cast<const float4*>(Ain + (ktb + r) * DD + mt + c4 * 4);
        } else {
            const int off = (ktb + r) * DD + mt + c4 * 4;
            float4 a = *reinterpret_cast<const float4*>(g_p1 + off);
            float4 b = *reinterpret_cast<const float4*>(g_p1 + KK * DD + off);
            float4 c = *reinterpret_cast<const float4*>(g_p1 + 2 * KK * DD + off);
            float4 d = *reinterpret_cast<const float4*>(g_p1 + 3 * KK * DD + off);
            *reinterpret_cast<float4*>(&As[r][c4 * 4]) =
                make_float4(a.x+b.x+c.x+d.x, a.y+b.y+c.y+d.y,
                            a.z+b.z+c.z+d.z, a.w+b.w+c.w+d.w);
        }
    }
#pragma unroll
    for (int s = 0; s < 16; ++s) {
        int idx = t + s * 128;
        if (!STAGE1) {                            // Bs[n][m] = Wq[nt+n][mt+m]
            int n = idx >> 5, c4 = idx & 31;
            *reinterpret_cast<float4*>(&BsA[n][c4 * 4]) =
                *reinterpret_cast<const float4*>(B + (nt + n) * DD + mt + c4 * 4);
        } else {                                  // Bs[m][n] = Wk[mt+m][nt+n]
            int m = idx >> 4, c4 = idx & 15;
            *reinterpret_cast<float4*>(&BsB[m][c4 * 4]) =
                *reinterpret_cast<const float4*>(B + (mt + m) * DD + nt + c4 * 4);
        }
    }
    __syncthreads();

    float acc[4][4];
#pragma unroll
    for (int i = 0; i < 4; ++i)
#pragma unroll
        for (int j = 0; j < 4; ++j) acc[i][j] = 0.f;

#pragma unroll 4
    for (int mg = 0; mg < 32; ++mg) {
        float4 a0 = *reinterpret_cast<const float4*>(&As[4 * kq + 0][4 * mg]);
        float4 a1 = *reinterpret_cast<const float4*>(&As[4 * kq + 1][4 * mg]);
        float4 a2 = *reinterpret_cast<const float4*>(&As[4 * kq + 2][4 * mg]);
        float4 a3 = *reinterpret_cast<const float4*>(&As[4 * kq + 3][4 * mg]);
        float4 av[4] = {a0, a1, a2, a3};
        if (!STAGE1) {
            float4 b0 = *reinterpret_cast<const float4*>(&BsA[4 * nq + 0][4 * mg]);
            float4 b1 = *reinterpret_cast<const float4*>(&BsA[4 * nq + 1][4 * mg]);
            float4 b2 = *reinterpret_cast<const float4*>(&BsA[4 * nq + 2][4 * mg]);
            float4 b3 = *reinterpret_cast<const float4*>(&BsA[4 * nq + 3][4 * mg]);
            float4 bv[4] = {b0, b1, b2, b3};
#pragma unroll
            for (int i = 0; i < 4; ++i)
#pragma unroll
                for (int j = 0; j < 4; ++j)
                    acc[i][j] += av[i].x * bv[j].x + av[i].y * bv[j].y
                               + av[i].z * bv[j].z + av[i].w * bv[j].w;
        } else {
            float4 b0 = *reinterpret_cast<const float4*>(&BsB[4 * mg + 0][4 * nq]);
            float4 b1 = *reinterpret_cast<const float4*>(&BsB[4 * mg + 1][4 * nq]);
            float4 b2 = *reinterpret_cast<const float4*>(&BsB[4 * mg + 2][4 * nq]);
            float4 b3 = *reinterpret_cast<const float4*>(&BsB[4 * mg + 3][4 * nq]);
#pragma unroll
            for (int i = 0; i < 4; ++i) {
                acc[i][0] += av[i].x * b0.x + av[i].y * b1.x + av[i].z * b2.x + av[i].w * b3.x;
                acc[i][1] += av[i].x * b0.y + av[i].y * b1.y + av[i].z * b2.y + av[i].w * b3.y;
                acc[i][2] += av[i].x * b0.z + av[i].y * b1.z + av[i].z * b2.z + av[i].w * b3.z;
                acc[i][3] += av[i].x * b0.w + av[i].y * b1.w + av[i].z * b2.w + av[i].w * b3.w;
            }
        }
    }

    float* Out = (STAGE1 ? g_p2 : g_p1) + (size_t)sp * KK * DD;
#pragma unroll
    for (int i = 0; i < 4; ++i) {
        int k = ktb + 4 * kq + i;
        *reinterpret_cast<float4*>(Out + k * DD + nt + 4 * nq) =
            make_float4(acc[i][0], acc[i][1], acc[i][2], acc[i][3]);
    }
}

// ---------------------------------------------------------------------------
// Fused compat + masked softmax. One 2-CTA cluster per row k.
// Grid 256 x 512 threads, cluster (2,1,1): blockIdx.x>>1 = k, &1 = half.
// Each CTA: 16 warps x 64 nodes = 1024 nodes. e values stay in smem.
// Half-sums exchanged via DSMEM + cluster.sync(); each CTA normalizes its
// half straight to out. No fences, no extra kernel. Fully deterministic.
// ---------------------------------------------------------------------------
__global__ void __launch_bounds__(512) __cluster_dims__(2, 1, 1)
compat_softmax(const float* __restrict__ nodep, const void* __restrict__ maskp,
               float* __restrict__ out) {
    __shared__ float evals[1024];
    __shared__ float wsums[16];
    __shared__ float ssum[2];

    cg::cluster_group cluster = cg::this_cluster();
    const unsigned rank = cluster.block_rank();          // == blockIdx.x & 1
    const int lane = threadIdx.x & 31;
    const int w    = threadIdx.x >> 5;                   // 0..15
    const int k    = blockIdx.x >> 1;
    const int half = blockIdx.x & 1;

    // q[k] = sum of 4 stage-2 split partials (per-warp register copy)
    const float4* p2 = reinterpret_cast<const float4*>(g_p2);
    float4 q0, q1, q2, q3;
    {
        const int rs = DD / 4;
#pragma unroll
        for (int seg = 0; seg < 4; ++seg) {
            float4 a0 = p2[(0 * KK + k) * rs + seg * 32 + lane];
            float4 b0 = p2[(1 * KK + k) * rs + seg * 32 + lane];
            float4 c0 = p2[(2 * KK + k) * rs + seg * 32 + lane];
            float4 d0 = p2[(3 * KK + k) * rs + seg * 32 + lane];
            float4 q = make_float4(a0.x+b0.x+c0.x+d0.x, a0.y+b0.y+c0.y+d0.y,
                                   a0.z+b0.z+c0.z+d0.z, a0.w+b0.w+c0.w+d0.w);
            if (seg == 0) q0 = q; else if (seg == 1) q1 = q;
            else if (seg == 2) q2 = q; else q3 = q;
        }
    }

    const bool mi32 = (g_mask_i32 != 0);
    float wacc = 0.f;

#pragma unroll
    for (int c = 0; c < 2; ++c) {
        const int nb = w * 64 + c * 32;                  // node within this CTA's half
        const int i0 = half * 1024 + nb;                 // node within row

        bool msk;
        if (mi32) {
            msk = __ldg(reinterpret_cast<const int*>(maskp) + k * NNODES + i0 + lane) != 0;
        } else {
            msk = __ldg(reinterpret_cast<const unsigned char*>(maskp) + k * NNODES + i0 + lane) != 0;
        }

        const float4* base = reinterpret_cast<const float4*>(nodep)
                           + ((size_t)(k * NNODES + i0) << 7);   // *128 float4/node

        float res = 0.f;
#pragma unroll 4
        for (int ii = 0; ii < 32; ++ii) {
            const float4* p = base + ((size_t)ii << 7);
            float4 v0 = __ldcs(p + lane);
            float4 v1 = __ldcs(p + 32 + lane);
            float4 v2 = __ldcs(p + 64 + lane);
            float4 v3 = __ldcs(p + 96 + lane);
            float a0 = v0.x * q0.x + v0.y * q0.y + v0.z * q0.z + v0.w * q0.w;
            float a1 = v1.x * q1.x + v1.y * q1.y + v1.z * q1.z + v1.w * q1.w;
            float a2 = v2.x * q2.x + v2.y * q2.y + v2.z * q2.z + v2.w * q2.w;
            float a3 = v3.x * q3.x + v3.y * q3.y + v3.z * q3.z + v3.w * q3.w;
            float a = (a0 + a1) + (a2 + a3);
#pragma unroll
            for (int off = 16; off; off >>= 1)
                a += __shfl_xor_sync(0xffffffffu, a, off);
            if (lane == ii) res = a;
        }

        float cl = fminf(10.f, fmaxf(-10.f, res));
        float v  = tanhf(cl) * 0.04419417382415922f;     // 1/sqrt(512)
        float e  = msk ? 0.f : __expf(v);
        evals[nb + lane] = e;

        float ws = e;
#pragma unroll
        for (int off = 16; off; off >>= 1)
            ws += __shfl_xor_sync(0xffffffffu, ws, off);
        wacc += ws;                                       // same value on all lanes
    }

    if (lane == 0) wsums[w] = wacc;
    __syncthreads();

    if (w == 0) {
        float s = (lane < 16) ? wsums[lane] : 0.f;
#pragma unroll
        for (int off = 16; off; off >>= 1)
            s += __shfl_xor_sync(0xffffffffu, s, off);
        if (lane == 0) {
            ssum[rank] = s;                               // my slot, local
            float* peer = cluster.map_shared_rank(ssum, rank ^ 1u);
            peer[rank] = s;                               // my slot, peer's smem
        }
    }
    cluster.sync();                                       // orders DSMEM writes

    const float inv = 1.0f / (ssum[0] + ssum[1]);
    const int t = threadIdx.x;
    float2 ev = *reinterpret_cast<const float2*>(&evals[2 * t]);
    float2* o2 = reinterpret_cast<float2*>(out + k * NNODES + half * 1024);
    o2[t] = make_float2(ev.x * inv, ev.y * inv);
}

extern "C" void kernel_launch(void* const* d_in, const int* in_sizes, int n_in,
                              void* d_out, int out_size) {
    const float* ctx  = (const float*)d_in[0];
    const float* node = (const float*)d_in[1];
    const void*  mask = d_in[2];
    const float* Wq   = (const float*)d_in[3];
    const float* Wk   = (const float*)d_in[4];
    float* out = (float*)d_out;
    (void)in_sizes; (void)n_in; (void)out_size;

    proj_gemm_rt<false><<<128, 128>>>(ctx, Wq, (const int*)mask);  // g_p1
    proj_gemm_rt<true ><<<128, 128>>>(nullptr, Wk, nullptr);       // g_p2
    compat_softmax<<<256, 512>>>(node, mask, out);                 // fused, clustered
}